// round 10
// baseline (speedup 1.0000x reference)
#include <cuda_runtime.h>
#include <cstddef>
#include <cstdint>

// FastNGramLM advance, round 10: batched TMA volley + direct global patch.
//  - dense next-plane row is IDENTICAL for all hyps -> build once, ship 8x
//  - score rows differ only by scalar acc_j -> build all 8 in one pass (32KB)
//  - ONE barrier, tid0 issues 16 cp.async.bulk + wait_group 0, ONE barrier,
//    then chain threads patch <=48 slots per hyp DIRECTLY in global memory
//    (3 depth-ordered STG rounds, deepest first = first-found-wins)
//  - barriers per block: 24 (R9) -> 6
//
// Output: d_out[0..B*V) = scores f32, d_out[B*V..2BV) = next as exact f32.

#define VMAX  1024
#define DEPTH 3
#define ARCS  16
#define HPB   8
#define TPB   256

__device__ __forceinline__ uint32_t smem_u32(const void* p) {
    return (uint32_t)__cvta_generic_to_shared(p);
}

__global__ __launch_bounds__(TPB, 6)
void ngram_fused_kernel(const float* __restrict__ arcs_weights,
                        const float* __restrict__ backoff_weights,
                        const int*   __restrict__ ilabels,
                        const int*   __restrict__ to_states,
                        const int*   __restrict__ backoff_to,
                        const int*   __restrict__ state_start,
                        const int*   __restrict__ state_end,
                        const int*   __restrict__ states,
                        float*       __restrict__ out_scores,
                        float*       __restrict__ out_next,
                        int B, int V)
{
    __shared__ __align__(128) float s_sc[HPB][VMAX];  // 8 score rows (32KB)
    __shared__ __align__(128) float s_nx[VMAX];       // one shared next row
    __shared__ float s_acc[HPB];

    const int tid = threadIdx.x;
    const int h0  = blockIdx.x * HPB;

    // ---- dense fallback -> registers ----
    const float4 wf  = __ldg((const float4*)arcs_weights + tid);
    const int4   nfi = __ldg((const int4*)  to_states    + tid);
    float4 nfv;
    nfv.x = (float)nfi.x; nfv.y = (float)nfi.y;
    nfv.z = (float)nfi.z; nfv.w = (float)nfi.w;

    // ---- chain phase: threads 0..127 = 8 hyps x 16 lanes, regs-resident ----
    int   lab[DEPTH];
    float scr[DEPTH];
    float nxf[DEPTH];
    if (tid < HPB * ARCS) {
        const int j    = tid >> 4;
        const int lane = tid & 15;
        const int h    = h0 + j;
        int   cur = (h < B) ? __ldg(&states[h]) : 0;
        float acc = 0.0f;
        #pragma unroll
        for (int d = 0; d < DEPTH; ++d) {
            lab[d] = -1; scr[d] = 0.0f; nxf[d] = 0.0f;
            if (cur != 0) {                    // START == 0
                const int st  = __ldg(&state_start[cur]);
                const int en  = __ldg(&state_end[cur]);
                const int idx = st + lane;
                if (idx < en) {
                    lab[d] = __ldg(&ilabels[idx]);
                    scr[d] = acc + __ldg(&arcs_weights[idx]);
                    nxf[d] = (float)__ldg(&to_states[idx]);
                }
                acc += __ldg(&backoff_weights[cur]);
                cur  = __ldg(&backoff_to[cur]);
            }
        }
        if (lane == 0) s_acc[j] = acc;
    }
    __syncthreads();   // s_acc ready                                  [1]

    // ---- build all 8 score rows + the shared next row ----
    const int lab0 = tid * 4;
    *(float4*)&s_nx[lab0] = nfv;
    #pragma unroll
    for (int j = 0; j < HPB; ++j) {
        const float acc = s_acc[j];
        float4 sc;
        sc.x = acc + wf.x; sc.y = acc + wf.y;
        sc.z = acc + wf.z; sc.w = acc + wf.w;
        *(float4*)&s_sc[j][lab0] = sc;
    }
    __syncthreads();   // staging complete                             [2]

    // ---- one TMA volley: 8 score rows + 8x the same next row ----
    if (tid == 0) {
        asm volatile("fence.proxy.async.shared::cta;" ::: "memory");
        const uint32_t snx = smem_u32(&s_nx[0]);
        #pragma unroll
        for (int j = 0; j < HPB; ++j) {
            const int h = h0 + j;
            if (h >= B) break;
            const size_t   row = (size_t)h * (size_t)V;
            const uint32_t ssc = smem_u32(&s_sc[j][0]);
            asm volatile(
                "cp.async.bulk.global.shared::cta.bulk_group [%0], [%1], %2;"
                :: "l"(out_scores + row), "r"(ssc), "r"(V * 4) : "memory");
            asm volatile(
                "cp.async.bulk.global.shared::cta.bulk_group [%0], [%1], %2;"
                :: "l"(out_next + row), "r"(snx), "r"(V * 4) : "memory");
        }
        asm volatile("cp.async.bulk.commit_group;" ::: "memory");
        asm volatile("cp.async.bulk.wait_group 0;" ::: "memory");  // writes done
    }
    __syncthreads();   // TMA writes complete, visible to all          [3]

    // ---- patch global directly: deepest -> shallowest ----
    const int    jh    = tid >> 4;
    const size_t hbase = (size_t)(h0 + jh) * (size_t)V;
    const bool   owner = (tid < HPB * ARCS) && (h0 + jh < B);

    #pragma unroll
    for (int d = DEPTH - 1; d >= 0; --d) {
        if (owner && lab[d] >= 0) {
            out_scores[hbase + lab[d]] = scr[d];
            out_next  [hbase + lab[d]] = nxf[d];
        }
        if (d > 0) __syncthreads();   // order depth rounds            [4][5]
    }
}

extern "C" void kernel_launch(void* const* d_in, const int* in_sizes, int n_in,
                              void* d_out, int out_size)
{
    // Classify inputs by element count (robust to metadata ordering):
    //   arcs group (3x largest):  arcs_weights, ilabels, to_states
    //   state group (4x middle):  backoff_weights, backoff_to, start, end
    //   states: the remaining batch-sized array
    long long max_sz = 0;
    for (int i = 0; i < n_in; ++i)
        if ((long long)in_sizes[i] > max_sz) max_sz = in_sizes[i];

    long long arc_sz = max_sz;
    long long n_sz = -1;
    for (int i = 0; i < n_in; ++i) {
        int cnt = 0;
        for (int j = 0; j < n_in; ++j)
            if (in_sizes[j] == in_sizes[i]) ++cnt;
        if (cnt == 4) { n_sz = in_sizes[i]; break; }
    }

    const void* arc_grp[3];  int na = 0;
    const void* st_grp[4];   int ns = 0;
    const void* states_ptr = nullptr;
    long long B = 0;
    for (int i = 0; i < n_in; ++i) {
        if (in_sizes[i] == arc_sz && na < 3)      arc_grp[na++] = d_in[i];
        else if (in_sizes[i] == n_sz && ns < 4)   st_grp[ns++]  = d_in[i];
        else { states_ptr = d_in[i]; B = in_sizes[i]; }
    }

    const float* arcs_weights    = (const float*)arc_grp[0];
    const int*   ilabels         = (const int*)  arc_grp[1];
    const int*   to_states       = (const int*)  arc_grp[2];
    const float* backoff_weights = (const float*)st_grp[0];
    const int*   backoff_to      = (const int*)  st_grp[1];
    const int*   state_start     = (const int*)  st_grp[2];
    const int*   state_end       = (const int*)  st_grp[3];
    const int*   states          = (const int*)  states_ptr;

    const long long V = (long long)out_size / (2 * B);
    float* out_scores = (float*)d_out;
    float* out_next   = (float*)d_out + (size_t)B * (size_t)V;

    const int grid = (int)((B + HPB - 1) / HPB);
    ngram_fused_kernel<<<grid, TPB>>>(
        arcs_weights, backoff_weights, ilabels, to_states,
        backoff_to, state_start, state_end, states,
        out_scores, out_next, (int)B, (int)V);
}

// round 11
// speedup vs baseline: 1.0700x; 1.0700x over previous
#include <cuda_runtime.h>
#include <cstddef>
#include <cstdint>

// FastNGramLM advance, round 11: warp-owned hypotheses, ONE block barrier.
//  - 256 threads = 8 warps; warp w owns hypothesis h0+w end-to-end:
//      chain (lanes 0..15, uniform) -> private 4KB score staging ->
//      syncwarp-ordered patch -> TMA ship (scores + shared next row).
//  - each staging buffer used ONCE -> no reuse waits in the loop
//  - shared next row (identical for every hypothesis) built once by all
//    threads; the only __syncthreads in the kernel orders it.
//  - acc is computed redundantly by all lanes (uniform loads) -> no smem.
//
// Output: d_out[0..B*V) = scores f32, d_out[B*V..2BV) = next as exact f32.

#define VMAX  1024
#define DEPTH 3
#define ARCS  16
#define HPB   8
#define TPB   256

__device__ __forceinline__ uint32_t smem_u32(const void* p) {
    return (uint32_t)__cvta_generic_to_shared(p);
}

__global__ __launch_bounds__(TPB, 6)
void ngram_fused_kernel(const float* __restrict__ arcs_weights,
                        const float* __restrict__ backoff_weights,
                        const int*   __restrict__ ilabels,
                        const int*   __restrict__ to_states,
                        const int*   __restrict__ backoff_to,
                        const int*   __restrict__ state_start,
                        const int*   __restrict__ state_end,
                        const int*   __restrict__ states,
                        float*       __restrict__ out_scores,
                        float*       __restrict__ out_next,
                        int B, int V)
{
    __shared__ __align__(128) float s_sc[HPB][VMAX];  // per-warp score rows
    __shared__ __align__(128) float s_nx[VMAX];       // shared next row

    const int tid  = threadIdx.x;
    const int w    = tid >> 5;          // warp id == hypothesis slot
    const int lane = tid & 31;
    const int h0   = blockIdx.x * HPB;
    const int h    = h0 + w;

    // ---- build shared next row (1 float4 per thread), independent ----
    {
        const int4 nfi = __ldg((const int4*)to_states + tid);
        float4 nfv;
        nfv.x = (float)nfi.x; nfv.y = (float)nfi.y;
        nfv.z = (float)nfi.z; nfv.w = (float)nfi.w;
        *(float4*)&s_nx[tid * 4] = nfv;
    }
    __syncthreads();   // the ONLY block barrier: next row complete

    // ---- chain: warp-uniform scalar walk; lanes 0..15 gather arcs ----
    int   lab[DEPTH];
    float scr[DEPTH];
    float nxf[DEPTH];
    float acc = 0.0f;
    {
        int cur = (h < B) ? __ldg(&states[h]) : 0;   // uniform in warp
        #pragma unroll
        for (int d = 0; d < DEPTH; ++d) {
            lab[d] = -1; scr[d] = 0.0f; nxf[d] = 0.0f;
            if (cur != 0) {                    // uniform branch
                const int st  = __ldg(&state_start[cur]);
                const int en  = __ldg(&state_end[cur]);
                const int idx = st + lane;
                if (lane < ARCS && idx < en) {
                    lab[d] = __ldg(&ilabels[idx]);
                    scr[d] = acc + __ldg(&arcs_weights[idx]);
                    nxf[d] = (float)__ldg(&to_states[idx]);
                }
                acc += __ldg(&backoff_weights[cur]);   // uniform
                cur  = __ldg(&backoff_to[cur]);        // uniform
            }
        }
    }

    if (h < B) {
        // ---- build this warp's score row: 8 float4 per lane ----
        float* row = s_sc[w];
        #pragma unroll
        for (int k = 0; k < 8; ++k) {
            const int o = k * 128 + lane * 4;
            const float4 wf4 = __ldg((const float4*)(arcs_weights + o));
            float4 sc;
            sc.x = acc + wf4.x; sc.y = acc + wf4.y;
            sc.z = acc + wf4.z; sc.w = acc + wf4.w;
            *(float4*)&row[o] = sc;
        }

        // ---- patch: deepest -> shallowest, syncwarp-ordered ----
        #pragma unroll
        for (int d = DEPTH - 1; d >= 0; --d) {
            if (lab[d] >= 0) {
                row[lab[d]]  = scr[d];
                s_nx_patch:;
            }
            __syncwarp();
        }
        // next-row patches go directly into the OUTPUT later? No: next row in
        // smem is shared across warps -- patch next values into the global row
        // after the TMA ship instead (see below).

        // ---- ship: scores row + shared next row -> this hyp's output ----
        __syncwarp();
        if (lane == 0) {
            asm volatile("fence.proxy.async.shared::cta;" ::: "memory");
            const size_t   g   = (size_t)h * (size_t)V;
            const uint32_t ssc = smem_u32(row);
            const uint32_t snx = smem_u32(&s_nx[0]);
            asm volatile(
                "cp.async.bulk.global.shared::cta.bulk_group [%0], [%1], %2;"
                :: "l"(out_scores + g), "r"(ssc), "r"(V * 4) : "memory");
            asm volatile(
                "cp.async.bulk.global.shared::cta.bulk_group [%0], [%1], %2;"
                :: "l"(out_next + g), "r"(snx), "r"(V * 4) : "memory");
            asm volatile("cp.async.bulk.commit_group;" ::: "memory");
            asm volatile("cp.async.bulk.wait_group 0;" ::: "memory");
        }
        __syncwarp();   // TMA writes of this hyp complete (lane0 waited)

        // ---- patch next-plane slots directly in global (deep -> shallow) ----
        const size_t g = (size_t)h * (size_t)V;
        #pragma unroll
        for (int d = DEPTH - 1; d >= 0; --d) {
            if (lab[d] >= 0)
                out_next[g + lab[d]] = nxf[d];
            __syncwarp();   // order depth rounds (warp-scope fence)
        }
    }
}

extern "C" void kernel_launch(void* const* d_in, const int* in_sizes, int n_in,
                              void* d_out, int out_size)
{
    // Classify inputs by element count (robust to metadata ordering):
    //   arcs group (3x largest):  arcs_weights, ilabels, to_states
    //   state group (4x middle):  backoff_weights, backoff_to, start, end
    //   states: the remaining batch-sized array
    long long max_sz = 0;
    for (int i = 0; i < n_in; ++i)
        if ((long long)in_sizes[i] > max_sz) max_sz = in_sizes[i];

    long long arc_sz = max_sz;
    long long n_sz = -1;
    for (int i = 0; i < n_in; ++i) {
        int cnt = 0;
        for (int j = 0; j < n_in; ++j)
            if (in_sizes[j] == in_sizes[i]) ++cnt;
        if (cnt == 4) { n_sz = in_sizes[i]; break; }
    }

    const void* arc_grp[3];  int na = 0;
    const void* st_grp[4];   int ns = 0;
    const void* states_ptr = nullptr;
    long long B = 0;
    for (int i = 0; i < n_in; ++i) {
        if (in_sizes[i] == arc_sz && na < 3)      arc_grp[na++] = d_in[i];
        else if (in_sizes[i] == n_sz && ns < 4)   st_grp[ns++]  = d_in[i];
        else { states_ptr = d_in[i]; B = in_sizes[i]; }
    }

    const float* arcs_weights    = (const float*)arc_grp[0];
    const int*   ilabels         = (const int*)  arc_grp[1];
    const int*   to_states       = (const int*)  arc_grp[2];
    const float* backoff_weights = (const float*)st_grp[0];
    const int*   backoff_to      = (const int*)  st_grp[1];
    const int*   state_start     = (const int*)  st_grp[2];
    const int*   state_end       = (const int*)  st_grp[3];
    const int*   states          = (const int*)  states_ptr;

    const long long V = (long long)out_size / (2 * B);
    float* out_scores = (float*)d_out;
    float* out_next   = (float*)d_out + (size_t)B * (size_t)V;

    const int grid = (int)((B + HPB - 1) / HPB);
    ngram_fused_kernel<<<grid, TPB>>>(
        arcs_weights, backoff_weights, ilabels, to_states,
        backoff_to, state_start, state_end, states,
        out_scores, out_next, (int)B, (int)V);
}

// round 12
// speedup vs baseline: 1.1031x; 1.0309x over previous
#include <cuda_runtime.h>
#include <cstddef>
#include <cstdint>

// FastNGramLM advance, round 12: fully decoupled warp pipelines.
//  - TPB=128 -> 4 warps/block; warp w owns hypothesis blockIdx*4+w END-TO-END
//  - per-warp PRIVATE score row AND next row in smem (8KB/warp, 32KB/block)
//  - warp life: chain -> build both rows (template LDGs are L1-hot) ->
//    patch both rows in smem (deep->shallow, syncwarp-ordered, shallow wins)
//    -> fence.proxy.async + 2x cp.async.bulk + commit -> single final
//    wait_group.read 0 (smem-reuse safety only).
//  - ZERO block barriers, ZERO mid-pipeline TMA waits, no post-ship STG.
//
// Output: d_out[0..B*V) = scores f32, d_out[B*V..2BV) = next as exact f32.

#define VMAX  1024
#define DEPTH 3
#define ARCS  16
#define HPB   4
#define TPB   128

__device__ __forceinline__ uint32_t smem_u32(const void* p) {
    return (uint32_t)__cvta_generic_to_shared(p);
}

__global__ __launch_bounds__(TPB)
void ngram_fused_kernel(const float* __restrict__ arcs_weights,
                        const float* __restrict__ backoff_weights,
                        const int*   __restrict__ ilabels,
                        const int*   __restrict__ to_states,
                        const int*   __restrict__ backoff_to,
                        const int*   __restrict__ state_start,
                        const int*   __restrict__ state_end,
                        const int*   __restrict__ states,
                        float*       __restrict__ out_scores,
                        float*       __restrict__ out_next,
                        int B, int V)
{
    __shared__ __align__(128) float s_sc[HPB][VMAX];   // private score rows
    __shared__ __align__(128) float s_nx[HPB][VMAX];   // private next rows

    const int tid  = threadIdx.x;
    const int w    = tid >> 5;
    const int lane = tid & 31;
    const int h    = blockIdx.x * HPB + w;

    // ---- chain: warp-uniform scalar walk; lanes 0..15 gather arcs ----
    int   lab[DEPTH];
    float scr[DEPTH];
    float nxf[DEPTH];
    float acc = 0.0f;
    {
        int cur = (h < B) ? __ldg(&states[h]) : 0;     // uniform in warp
        #pragma unroll
        for (int d = 0; d < DEPTH; ++d) {
            lab[d] = -1; scr[d] = 0.0f; nxf[d] = 0.0f;
            if (cur != 0) {                            // uniform branch
                const int st  = __ldg(&state_start[cur]);
                const int en  = __ldg(&state_end[cur]);
                const int idx = st + lane;
                if (lane < ARCS && idx < en) {
                    lab[d] = __ldg(&ilabels[idx]);
                    scr[d] = acc + __ldg(&arcs_weights[idx]);
                    nxf[d] = (float)__ldg(&to_states[idx]);
                }
                acc += __ldg(&backoff_weights[cur]);   // uniform
                cur  = __ldg(&backoff_to[cur]);        // uniform
            }
        }
    }

    if (h < B) {
        float* rs = s_sc[w];
        float* rn = s_nx[w];

        // ---- build both rows: 8 float4 per lane per plane (L1-hot LDGs) ----
        #pragma unroll
        for (int k = 0; k < VMAX / 128; ++k) {
            const int o = k * 128 + lane * 4;
            const float4 wf4 = __ldg((const float4*)(arcs_weights + o));
            const int4   nf4 = __ldg((const int4*)  (to_states    + o));
            float4 sc, nx;
            sc.x = acc + wf4.x; sc.y = acc + wf4.y;
            sc.z = acc + wf4.z; sc.w = acc + wf4.w;
            nx.x = (float)nf4.x; nx.y = (float)nf4.y;
            nx.z = (float)nf4.z; nx.w = (float)nf4.w;
            *(float4*)&rs[o] = sc;
            *(float4*)&rn[o] = nx;
        }
        __syncwarp();   // dense build visible within warp

        // ---- patch both rows in smem: deepest -> shallowest ----
        #pragma unroll
        for (int d = DEPTH - 1; d >= 0; --d) {
            if (lab[d] >= 0) {
                rs[lab[d]] = scr[d];
                rn[lab[d]] = nxf[d];
            }
            __syncwarp();   // order depth rounds (shallow lands last)
        }

        // ---- ship: 2 bulk copies, no completion wait on the hot path ----
        if (lane == 0) {
            asm volatile("fence.proxy.async.shared::cta;" ::: "memory");
            const size_t   g   = (size_t)h * (size_t)V;
            const uint32_t ssc = smem_u32(rs);
            const uint32_t snx = smem_u32(rn);
            asm volatile(
                "cp.async.bulk.global.shared::cta.bulk_group [%0], [%1], %2;"
                :: "l"(out_scores + g), "r"(ssc), "r"(V * 4) : "memory");
            asm volatile(
                "cp.async.bulk.global.shared::cta.bulk_group [%0], [%1], %2;"
                :: "l"(out_next + g), "r"(snx), "r"(V * 4) : "memory");
            asm volatile("cp.async.bulk.commit_group;" ::: "memory");
            // smem-reuse safety: reads must finish before CTA exit
            asm volatile("cp.async.bulk.wait_group.read 0;" ::: "memory");
        }
    }
}

extern "C" void kernel_launch(void* const* d_in, const int* in_sizes, int n_in,
                              void* d_out, int out_size)
{
    // Classify inputs by element count (robust to metadata ordering):
    //   arcs group (3x largest):  arcs_weights, ilabels, to_states
    //   state group (4x middle):  backoff_weights, backoff_to, start, end
    //   states: the remaining batch-sized array
    long long max_sz = 0;
    for (int i = 0; i < n_in; ++i)
        if ((long long)in_sizes[i] > max_sz) max_sz = in_sizes[i];

    long long arc_sz = max_sz;
    long long n_sz = -1;
    for (int i = 0; i < n_in; ++i) {
        int cnt = 0;
        for (int j = 0; j < n_in; ++j)
            if (in_sizes[j] == in_sizes[i]) ++cnt;
        if (cnt == 4) { n_sz = in_sizes[i]; break; }
    }

    const void* arc_grp[3];  int na = 0;
    const void* st_grp[4];   int ns = 0;
    const void* states_ptr = nullptr;
    long long B = 0;
    for (int i = 0; i < n_in; ++i) {
        if (in_sizes[i] == arc_sz && na < 3)      arc_grp[na++] = d_in[i];
        else if (in_sizes[i] == n_sz && ns < 4)   st_grp[ns++]  = d_in[i];
        else { states_ptr = d_in[i]; B = in_sizes[i]; }
    }

    const float* arcs_weights    = (const float*)arc_grp[0];
    const int*   ilabels         = (const int*)  arc_grp[1];
    const int*   to_states       = (const int*)  arc_grp[2];
    const float* backoff_weights = (const float*)st_grp[0];
    const int*   backoff_to      = (const int*)  st_grp[1];
    const int*   state_start     = (const int*)  st_grp[2];
    const int*   state_end       = (const int*)  st_grp[3];
    const int*   states          = (const int*)  states_ptr;

    const long long V = (long long)out_size / (2 * B);
    float* out_scores = (float*)d_out;
    float* out_next   = (float*)d_out + (size_t)B * (size_t)V;

    const int grid = (int)((B + HPB - 1) / HPB);
    ngram_fused_kernel<<<grid, TPB>>>(
        arcs_weights, backoff_weights, ilabels, to_states,
        backoff_to, state_start, state_end, states,
        out_scores, out_next, (int)B, (int)V);
}

// round 13
// speedup vs baseline: 1.1127x; 1.0087x over previous
#include <cuda_runtime.h>
#include <cstddef>
#include <cstdint>

// FastNGramLM advance, round 13: rotating score buffers + shared next
// template + deferred global next-patches.
//  - 256 threads, HPB=8, grid=1024 (single wave, 8 blocks/SM)
//  - next-plane template staged ONCE (4KB); TMA ships the same buffer for
//    every hypothesis; per-hyp next patches deferred to global STG at
//    iteration j+3, when wait_group 2 has already proven group j landed.
//  - score rows rotate over 4 buffers (16KB); wait_group 2 -> depth-3
//    pipeline, waits almost never block.
//  - 2 block barriers per hypothesis (was 3 in R9), 1 STS.128/thread build.
//
// Output: d_out[0..B*V) = scores f32, d_out[B*V..2BV) = next as exact f32.

#define VMAX  1024
#define DEPTH 3
#define ARCS  16
#define HPB   8
#define TPB   256
#define NBUF  4

__device__ __forceinline__ uint32_t smem_u32(const void* p) {
    return (uint32_t)__cvta_generic_to_shared(p);
}

__global__ __launch_bounds__(TPB, 8)
void ngram_fused_kernel(const float* __restrict__ arcs_weights,
                        const float* __restrict__ backoff_weights,
                        const int*   __restrict__ ilabels,
                        const int*   __restrict__ to_states,
                        const int*   __restrict__ backoff_to,
                        const int*   __restrict__ state_start,
                        const int*   __restrict__ state_end,
                        const int*   __restrict__ states,
                        float*       __restrict__ out_scores,
                        float*       __restrict__ out_next,
                        int B, int V)
{
    __shared__ __align__(128) float s_sc[NBUF][VMAX];      // rotating score rows
    __shared__ __align__(128) float s_nx[VMAX];            // shared next template
    __shared__ int   s_lab[HPB][DEPTH][ARCS];
    __shared__ float s_scr[HPB][DEPTH][ARCS];
    __shared__ float s_nxt[HPB][DEPTH][ARCS];
    __shared__ float s_acc[HPB];

    const int tid  = threadIdx.x;
    const int w    = tid >> 5;
    const int lane = tid & 31;
    const int h0   = blockIdx.x * HPB;

    // ---- dense fallback: weights -> regs, next template -> smem ----
    const float4 wf  = __ldg((const float4*)arcs_weights + tid);
    {
        const int4 nfi = __ldg((const int4*)to_states + tid);
        float4 nfv;
        nfv.x = (float)nfi.x; nfv.y = (float)nfi.y;
        nfv.z = (float)nfi.z; nfv.w = (float)nfi.w;
        *(float4*)&s_nx[tid * 4] = nfv;
    }

    // ---- chain phase: threads 0..127 = 8 hyps x 16 lanes -> smem records ----
    if (tid < HPB * ARCS) {
        const int j  = tid >> 4;
        const int ln = tid & 15;
        const int h  = h0 + j;
        int   cur = (h < B) ? __ldg(&states[h]) : 0;
        float acc = 0.0f;
        #pragma unroll
        for (int d = 0; d < DEPTH; ++d) {
            int lb = -1; float sv = 0.0f, nv = 0.0f;
            if (cur != 0) {                    // START == 0
                const int st  = __ldg(&state_start[cur]);
                const int en  = __ldg(&state_end[cur]);
                const int idx = st + ln;
                if (idx < en) {
                    lb = __ldg(&ilabels[idx]);
                    sv = acc + __ldg(&arcs_weights[idx]);
                    nv = (float)__ldg(&to_states[idx]);
                }
                acc += __ldg(&backoff_weights[cur]);
                cur  = __ldg(&backoff_to[cur]);
            }
            s_lab[j][d][ln] = lb;
            s_scr[j][d][ln] = sv;
            s_nxt[j][d][ln] = nv;
        }
        if (ln == 0) s_acc[j] = acc;
    }
    __syncthreads();   // template + records + acc ready

    const int lab0 = tid * 4;

    for (int j = 0; j < HPB; ++j) {
        const int h = h0 + j;
        const int p = j & (NBUF - 1);

        // ---- warp 1: deferred global next-patches for hyp j-3 ----
        // (group j-3 fully complete: tid0's wait_group 2 at iter j-1
        //  guaranteed groups <= j-3; barrier ordered us after it)
        if (w == 1 && j >= 3) {
            const int jj = j - 3;
            const int hh = h0 + jj;
            if (hh < B) {
                const size_t g = (size_t)hh * (size_t)V;
                #pragma unroll
                for (int d = DEPTH - 1; d >= 0; --d) {
                    if (lane < ARCS) {
                        const int lb = s_lab[jj][d][lane];
                        if (lb >= 0) out_next[g + lb] = s_nxt[jj][d][lane];
                    }
                    __syncwarp();   // shallow lands last
                }
            }
        }

        // ---- all threads: build score row p (1 float4 each) ----
        {
            const float acc = s_acc[j];
            float4 sc;
            sc.x = acc + wf.x; sc.y = acc + wf.y;
            sc.z = acc + wf.z; sc.w = acc + wf.w;
            *(float4*)&s_sc[p][lab0] = sc;
        }
        __syncthreads();   // build visible to warp 0                    [1]

        // ---- warp 0: patch score row, then tid0 ships ----
        if (w == 0) {
            #pragma unroll
            for (int d = DEPTH - 1; d >= 0; --d) {
                if (lane < ARCS) {
                    const int lb = s_lab[j][d][lane];
                    if (lb >= 0) s_sc[p][lb] = s_scr[j][d][lane];
                }
                __syncwarp();   // order depth rounds (shallow wins)
            }
            if (lane == 0 && h < B) {
                asm volatile("fence.proxy.async.shared::cta;" ::: "memory");
                const size_t   g   = (size_t)h * (size_t)V;
                const uint32_t ssc = smem_u32(&s_sc[p][0]);
                const uint32_t snx = smem_u32(&s_nx[0]);
                asm volatile(
                    "cp.async.bulk.global.shared::cta.bulk_group [%0], [%1], %2;"
                    :: "l"(out_scores + g), "r"(ssc), "r"(V * 4) : "memory");
                asm volatile(
                    "cp.async.bulk.global.shared::cta.bulk_group [%0], [%1], %2;"
                    :: "l"(out_next + g), "r"(snx), "r"(V * 4) : "memory");
                asm volatile("cp.async.bulk.commit_group;" ::: "memory");
                // depth-3 pipeline: groups <= j-2 fully complete
                asm volatile("cp.async.bulk.wait_group 2;" ::: "memory");
            }
        }
        __syncthreads();                                               // [2]
    }

    // ---- tail: drain, then patch next-plane of last 3 hypotheses ----
    if (tid == 0)
        asm volatile("cp.async.bulk.wait_group 0;" ::: "memory");
    __syncthreads();

    if (w >= 1 && w <= 3) {            // warps 1..3 -> hyps HPB-3..HPB-1
        const int jj = HPB - 4 + w;
        const int hh = h0 + jj;
        if (hh < B) {
            const size_t g = (size_t)hh * (size_t)V;
            #pragma unroll
            for (int d = DEPTH - 1; d >= 0; --d) {
                if (lane < ARCS) {
                    const int lb = s_lab[jj][d][lane];
                    if (lb >= 0) out_next[g + lb] = s_nxt[jj][d][lane];
                }
                __syncwarp();
            }
        }
    }
}

extern "C" void kernel_launch(void* const* d_in, const int* in_sizes, int n_in,
                              void* d_out, int out_size)
{
    // Classify inputs by element count (robust to metadata ordering):
    //   arcs group (3x largest):  arcs_weights, ilabels, to_states
    //   state group (4x middle):  backoff_weights, backoff_to, start, end
    //   states: the remaining batch-sized array
    long long max_sz = 0;
    for (int i = 0; i < n_in; ++i)
        if ((long long)in_sizes[i] > max_sz) max_sz = in_sizes[i];

    long long arc_sz = max_sz;
    long long n_sz = -1;
    for (int i = 0; i < n_in; ++i) {
        int cnt = 0;
        for (int j = 0; j < n_in; ++j)
            if (in_sizes[j] == in_sizes[i]) ++cnt;
        if (cnt == 4) { n_sz = in_sizes[i]; break; }
    }

    const void* arc_grp[3];  int na = 0;
    const void* st_grp[4];   int ns = 0;
    const void* states_ptr = nullptr;
    long long B = 0;
    for (int i = 0; i < n_in; ++i) {
        if (in_sizes[i] == arc_sz && na < 3)      arc_grp[na++] = d_in[i];
        else if (in_sizes[i] == n_sz && ns < 4)   st_grp[ns++]  = d_in[i];
        else { states_ptr = d_in[i]; B = in_sizes[i]; }
    }

    const float* arcs_weights    = (const float*)arc_grp[0];
    const int*   ilabels         = (const int*)  arc_grp[1];
    const int*   to_states       = (const int*)  arc_grp[2];
    const float* backoff_weights = (const float*)st_grp[0];
    const int*   backoff_to      = (const int*)  st_grp[1];
    const int*   state_start     = (const int*)  st_grp[2];
    const int*   state_end       = (const int*)  st_grp[3];
    const int*   states          = (const int*)  states_ptr;

    const long long V = (long long)out_size / (2 * B);
    float* out_scores = (float*)d_out;
    float* out_next   = (float*)d_out + (size_t)B * (size_t)V;

    const int grid = (int)((B + HPB - 1) / HPB);
    ngram_fused_kernel<<<grid, TPB>>>(
        arcs_weights, backoff_weights, ilabels, to_states,
        backoff_to, state_start, state_end, states,
        out_scores, out_next, (int)B, (int)V);
}